// round 6
// baseline (speedup 1.0000x reference)
#include <cuda_runtime.h>
#include <math.h>

// Shapes (fixed for this problem)
#define BATCH 16
#define SEQL  128
#define DIM   768
#define NH1   770
#define NOUT  40
#define NPAIR 3405
#define LP1   129     // L+1 rows per batch in hidden_states
#define PST   772     // padded row stride for P/Q (float4-aligned)

// Scratch: P = X @ W1i, Q = X @ W1j (X = hidden[:,1:129,:] flattened, 2048 rows).
// Columns 770..771 are written as zeros by gemm1 (guarded B loads produce 0 acc).
__device__ float g_P[(size_t)BATCH * SEQL * PST + 64];
__device__ float g_Q[(size_t)BATCH * SEQL * PST + 64];

// ---------------------------------------------------------------------------
// Kernel 1: 2048 x 768 x 770 fp32 GEMM. z=0 -> P, z=1 -> Q.
// 128x96 tile, 128 threads, 8x12 micro-tile (0.83 smem-B/FMA), BK=16,
// single-sync double buffer. Grid = 9*16*2 = 288 blocks = one balanced wave.
// ---------------------------------------------------------------------------
#define BM 128
#define BN 96
#define BK 16
#define NKT (DIM / BK)   // 48

__global__ __launch_bounds__(128, 2)
void gemm1_kernel(const float* __restrict__ hidden, const float* __restrict__ W1) {
    const int n0 = blockIdx.x * BN;
    const int m0 = blockIdx.y * BM;
    const float* W = W1 + (size_t)blockIdx.z * DIM * NH1;
    float* Cout = (blockIdx.z == 0) ? g_P : g_Q;

    __shared__ float As[2][BK][BM];
    __shared__ float Bs[2][BK][BN];

    const int tid = threadIdx.x;
    const int tx  = tid & 7;    // 8 col groups x 12 cols
    const int ty  = tid >> 3;   // 16 row groups x 8 rows

    float acc[8][12];
    #pragma unroll
    for (int i = 0; i < 8; i++)
        #pragma unroll
        for (int j = 0; j < 12; j++) acc[i][j] = 0.f;

    // A-load: 128 rows x 16 k = 4 float4 per thread
    const int a_k4 = tid & 3;    // float4 index within 16-wide k slab
    const int a_r  = tid >> 2;   // rows a_r + 32*rr
    const float* aptr[4];
    #pragma unroll
    for (int rr = 0; rr < 4; rr++) {
        int m = m0 + a_r + rr * 32;
        int bb = m >> 7, t = m & 127;
        aptr[rr] = hidden + (size_t)(bb * LP1 + t + 1) * DIM + a_k4 * 4;
    }

    // B-load: 16 k x 96 n = 12 scalars per thread (4 k-rows x 3 col-slots)
    const int lk   = tid >> 5;   // k rows lk + 4*k2
    const int lcol = tid & 31;   // cols lcol + 32*c
    bool bok[3];
    const float* bptr[3];
    #pragma unroll
    for (int c = 0; c < 3; c++) {
        int gc = n0 + lcol + 32 * c;
        bok[c]  = gc < NH1;
        bptr[c] = W + (bok[c] ? gc : 0);
    }

    float4 ra[4];
    float  rb[12];

    // prologue: tile 0 into buffer 0
    #pragma unroll
    for (int rr = 0; rr < 4; rr++) ra[rr] = *(const float4*)(aptr[rr]);
    #pragma unroll
    for (int k2 = 0; k2 < 4; k2++)
        #pragma unroll
        for (int c = 0; c < 3; c++)
            rb[k2*3+c] = bok[c] ? bptr[c][(size_t)(lk + 4*k2) * NH1] : 0.f;
    #pragma unroll
    for (int rr = 0; rr < 4; rr++) {
        As[0][a_k4*4+0][a_r + rr*32] = ra[rr].x;
        As[0][a_k4*4+1][a_r + rr*32] = ra[rr].y;
        As[0][a_k4*4+2][a_r + rr*32] = ra[rr].z;
        As[0][a_k4*4+3][a_r + rr*32] = ra[rr].w;
    }
    #pragma unroll
    for (int k2 = 0; k2 < 4; k2++)
        #pragma unroll
        for (int c = 0; c < 3; c++)
            Bs[0][lk + 4*k2][lcol + 32*c] = rb[k2*3+c];
    __syncthreads();

    int cur = 0;
    for (int kt = 0; kt < NKT; kt++) {
        const int k0n = (kt + 1) * BK;
        if (kt + 1 < NKT) {
            #pragma unroll
            for (int rr = 0; rr < 4; rr++) ra[rr] = *(const float4*)(aptr[rr] + k0n);
            #pragma unroll
            for (int k2 = 0; k2 < 4; k2++)
                #pragma unroll
                for (int c = 0; c < 3; c++)
                    rb[k2*3+c] = bok[c] ? bptr[c][(size_t)(k0n + lk + 4*k2) * NH1] : 0.f;
        }

        #pragma unroll
        for (int kk = 0; kk < BK; kk++) {
            float4 a0 = *(const float4*)&As[cur][kk][ty*8];
            float4 a1 = *(const float4*)&As[cur][kk][ty*8 + 4];
            float4 b0 = *(const float4*)&Bs[cur][kk][tx*12];
            float4 b1 = *(const float4*)&Bs[cur][kk][tx*12 + 4];
            float4 b2 = *(const float4*)&Bs[cur][kk][tx*12 + 8];
            float av[8]  = {a0.x,a0.y,a0.z,a0.w,a1.x,a1.y,a1.z,a1.w};
            float bv[12] = {b0.x,b0.y,b0.z,b0.w,b1.x,b1.y,b1.z,b1.w,b2.x,b2.y,b2.z,b2.w};
            #pragma unroll
            for (int i = 0; i < 8; i++)
                #pragma unroll
                for (int j = 0; j < 12; j++)
                    acc[i][j] = fmaf(av[i], bv[j], acc[i][j]);
        }

        if (kt + 1 < NKT) {
            int nxt = cur ^ 1;
            #pragma unroll
            for (int rr = 0; rr < 4; rr++) {
                As[nxt][a_k4*4+0][a_r + rr*32] = ra[rr].x;
                As[nxt][a_k4*4+1][a_r + rr*32] = ra[rr].y;
                As[nxt][a_k4*4+2][a_r + rr*32] = ra[rr].z;
                As[nxt][a_k4*4+3][a_r + rr*32] = ra[rr].w;
            }
            #pragma unroll
            for (int k2 = 0; k2 < 4; k2++)
                #pragma unroll
                for (int c = 0; c < 3; c++)
                    Bs[nxt][lk + 4*k2][lcol + 32*c] = rb[k2*3+c];
        }
        __syncthreads();
        cur ^= 1;
    }

    // Store. Cols >= 770 carry acc==0 (guarded B loads) -> writing the float4
    // covering 768..771 zeroes the pad columns for free. Skip nn >= 772.
    #pragma unroll
    for (int i = 0; i < 8; i++) {
        size_t mrow = (size_t)(m0 + ty*8 + i) * PST;
        #pragma unroll
        for (int jj = 0; jj < 3; jj++) {
            int nn = n0 + tx*12 + jj*4;
            if (nn + 3 < PST) {
                float4 v = make_float4(acc[i][jj*4+0], acc[i][jj*4+1],
                                       acc[i][jj*4+2], acc[i][jj*4+3]);
                *(float4*)(Cout + mrow + nn) = v;
            }
        }
    }
}

// ---------------------------------------------------------------------------
// Kernel 2: per (batch, 128-pair chunk):
//   Ht[k][r] = relu(P[vi_r][k] + Q[vj_r][k] + ind_r*w1c[k] + b1[k])
//   logits   = Ht^T @ W2 + b2, log_softmax fused via 4-lane shuffles.
// 64 threads, 8x10 register micro-tile (0.9 smem-B/FMA), K tiles of 32.
// ---------------------------------------------------------------------------
#define BP  128
#define BK2 32
#define HTS (BP + 4)   // 132, float4-aligned rows

__global__ __launch_bounds__(64, 8)
void span_head_kernel(const float* __restrict__ W1, const float* __restrict__ bias1,
                      const float* __restrict__ W2, const float* __restrict__ bias2,
                      const int* __restrict__ spans, float* __restrict__ out) {
    const int b   = blockIdx.y;
    const int p0  = blockIdx.x * BP;
    const int tid = threadIdx.x;   // 0..63

    __shared__ float Ht[BK2][HTS];
    __shared__ float W2s[BK2 * NOUT];
    __shared__ int   s_ri[BP];
    __shared__ int   s_rj[BP];
    __shared__ float s_ind[BP];

    const float* w1c = W1 + (size_t)2 * DIM * NH1;  // row 1536 of W1

    // Analytic pair decode: nonzero order of the (j>=i, j-i<30) band, L=128.
    #pragma unroll
    for (int t = tid; t < BP; t += 64) {
        int p  = p0 + t;
        int pc = (p < NPAIR) ? p : (NPAIR - 1);
        int i, j;
        if (pc < 2970) {
            i = pc / 30;
            j = i + (pc - 30 * i);
        } else {
            int q = pc - 2970;                        // 0..434, tail rows 99..127
            int d = (int)(29.5f - sqrtf(870.25f - 2.0f * (float)q));
            while ((d + 1) * (58 - d) / 2 <= q) d++;
            while (d * (59 - d) / 2 > q) d--;
            i = 99 + d;
            j = i + (q - d * (59 - d) / 2);
        }
        float ind = 0.f;
        if (p < NPAIR) {
            int s = spans[b*2 + 0];
            int e = spans[b*2 + 1];
            if (i == s && j == e)      ind = 2.f;
            else if (i >= s && j <= e) ind = 1.f;
        }
        s_ri[t]  = (b * SEQL + i) * PST;
        s_rj[t]  = (b * SEQL + j) * PST;
        s_ind[t] = ind;
    }
    __syncthreads();

    const int tx   = tid & 3;    // 4 col groups x 10 outputs
    const int ty   = tid >> 2;   // 16 row groups x 8 pairs
    const int g_kq = tid >> 3;   // float4 index within 32-wide k slab (0..7)
    const int g_r0 = tid & 7;    // gather rows g_r0 + 8w

    float acc[8][10];
    #pragma unroll
    for (int i = 0; i < 8; i++)
        #pragma unroll
        for (int j = 0; j < 10; j++) acc[i][j] = 0.f;

    for (int k0 = 0; k0 < NH1; k0 += BK2) {
        // W2 tile: 32x40 = 1280 floats = 320 float4 (5 per thread), coalesced.
        #pragma unroll
        for (int u = 0; u < 5; u++) {
            int idx4 = u * 64 + tid;
            int g    = k0 * NOUT + idx4 * 4;
            float4 v = make_float4(0.f, 0.f, 0.f, 0.f);
            if (g + 3 < NH1 * NOUT) v = *(const float4*)(W2 + g);
            *(float4*)&W2s[idx4 * 4] = v;
        }

        const int kb = k0 + g_kq * 4;
        const int kl = g_kq * 4;
        if (kb < PST) {   // kb <= 768: P/Q cols valid (770/771 are zeros)
            float4 c1, c2;
            if (kb + 3 < NH1) {
                c1 = *(const float4*)(w1c + kb);
                c2 = *(const float4*)(bias1 + kb);
            } else {
                c1.x = (kb+0 < NH1) ? w1c[kb+0] : 0.f;
                c1.y = (kb+1 < NH1) ? w1c[kb+1] : 0.f;
                c1.z = (kb+2 < NH1) ? w1c[kb+2] : 0.f;
                c1.w = (kb+3 < NH1) ? w1c[kb+3] : 0.f;
                c2.x = (kb+0 < NH1) ? bias1[kb+0] : 0.f;
                c2.y = (kb+1 < NH1) ? bias1[kb+1] : 0.f;
                c2.z = (kb+2 < NH1) ? bias1[kb+2] : 0.f;
                c2.w = (kb+3 < NH1) ? bias1[kb+3] : 0.f;
            }
            #pragma unroll
            for (int w = 0; w < 16; w++) {
                int r = g_r0 + w * 8;
                float4 p4 = *(const float4*)(g_P + s_ri[r] + kb);
                float4 q4 = *(const float4*)(g_Q + s_rj[r] + kb);
                float ind = s_ind[r];
                Ht[kl+0][r] = fmaxf(fmaf(ind, c1.x, p4.x + q4.x + c2.x), 0.f);
                Ht[kl+1][r] = fmaxf(fmaf(ind, c1.y, p4.y + q4.y + c2.y), 0.f);
                Ht[kl+2][r] = fmaxf(fmaf(ind, c1.z, p4.z + q4.z + c2.z), 0.f);
                Ht[kl+3][r] = fmaxf(fmaf(ind, c1.w, p4.w + q4.w + c2.w), 0.f);
            }
        } else {          // k >= 772: P/Q pad never touched — write zeros
            #pragma unroll
            for (int w = 0; w < 16; w++) {
                int r = g_r0 + w * 8;
                Ht[kl+0][r] = 0.f; Ht[kl+1][r] = 0.f;
                Ht[kl+2][r] = 0.f; Ht[kl+3][r] = 0.f;
            }
        }
        __syncthreads();

        #pragma unroll
        for (int kk = 0; kk < BK2; kk++) {
            float4 a0 = *(const float4*)&Ht[kk][ty*8];
            float4 a1 = *(const float4*)&Ht[kk][ty*8 + 4];
            const float* wrow = &W2s[kk * NOUT + tx * 10];
            float2 w0 = *(const float2*)(wrow + 0);
            float2 w1 = *(const float2*)(wrow + 2);
            float2 w2 = *(const float2*)(wrow + 4);
            float2 w3 = *(const float2*)(wrow + 6);
            float2 w4 = *(const float2*)(wrow + 8);
            float av[8]  = {a0.x,a0.y,a0.z,a0.w,a1.x,a1.y,a1.z,a1.w};
            float bv[10] = {w0.x,w0.y,w1.x,w1.y,w2.x,w2.y,w3.x,w3.y,w4.x,w4.y};
            #pragma unroll
            for (int i = 0; i < 8; i++)
                #pragma unroll
                for (int j = 0; j < 10; j++)
                    acc[i][j] = fmaf(av[i], bv[j], acc[i][j]);
        }
        __syncthreads();
    }

    // bias + log_softmax per row via 4-lane butterfly (lanes tx=0..3, same ty),
    // store straight from registers.
    float bb[10];
    #pragma unroll
    for (int j = 0; j < 10; j++) bb[j] = bias2[tx*10 + j];

    #pragma unroll
    for (int i = 0; i < 8; i++) {
        float l[10];
        #pragma unroll
        for (int j = 0; j < 10; j++) l[j] = acc[i][j] + bb[j];
        float mx = l[0];
        #pragma unroll
        for (int j = 1; j < 10; j++) mx = fmaxf(mx, l[j]);
        mx = fmaxf(mx, __shfl_xor_sync(0xffffffffu, mx, 1));
        mx = fmaxf(mx, __shfl_xor_sync(0xffffffffu, mx, 2));
        float sm = 0.f;
        #pragma unroll
        for (int j = 0; j < 10; j++) sm += expf(l[j] - mx);
        sm += __shfl_xor_sync(0xffffffffu, sm, 1);
        sm += __shfl_xor_sync(0xffffffffu, sm, 2);
        float lse = mx + logf(sm);

        int p_row = p0 + ty*8 + i;
        if (p_row < NPAIR) {
            float* op = out + ((size_t)b * NPAIR + p_row) * NOUT + tx * 10;
            #pragma unroll
            for (int j = 0; j < 5; j++) {
                float2 v = make_float2(l[j*2] - lse, l[j*2+1] - lse);
                *(float2*)(op + j*2) = v;
            }
        }
    }
}

// ---------------------------------------------------------------------------
// Launch. Inputs (metadata order): hidden_states, pred_spans, token_num,
// span_available_indication_matrix, W1, b1, W2, b2. Output fp32 [16,3405,40].
// ---------------------------------------------------------------------------
extern "C" void kernel_launch(void* const* d_in, const int* in_sizes, int n_in,
                              void* d_out, int out_size) {
    const float* hidden = (const float*)d_in[0];
    const int*   spans  = (const int*)d_in[1];
    const float* W1 = (const float*)d_in[4];
    const float* b1 = (const float*)d_in[5];
    const float* W2 = (const float*)d_in[6];
    const float* b2 = (const float*)d_in[7];
    float* out = (float*)d_out;

    gemm1_kernel<<<dim3((NH1 + BN - 1) / BN, (BATCH * SEQL) / BM, 2), 128>>>(hidden, W1);
    span_head_kernel<<<dim3((NPAIR + BP - 1) / BP, BATCH), 64>>>(W1, b1, W2, b2, spans, out);
}

// round 7
// speedup vs baseline: 1.2026x; 1.2026x over previous
#include <cuda_runtime.h>
#include <math.h>

// Shapes (fixed for this problem)
#define BATCH 16
#define SEQL  128
#define DIM   768
#define NH1   770
#define NOUT  40
#define NPAIR 3405
#define LP1   129     // L+1 rows per batch in hidden_states
#define PST   772     // padded row stride for P/Q (float4-aligned)

// Scratch: P = X @ W1i, Q = X @ W1j (X = hidden[:,1:129,:] flattened, 2048 rows).
// Columns 770..771 are written as zeros by gemm1 (guarded B loads produce 0 acc).
__device__ float g_P[(size_t)BATCH * SEQL * PST + 64];
__device__ float g_Q[(size_t)BATCH * SEQL * PST + 64];

// ---------------------------------------------------------------------------
// Kernel 1 (unchanged from R5 — measured ~90us): 2048 x 768 x 770 fp32 GEMM.
// z=0 -> P, z=1 -> Q. 128x96 tile, 128 threads, 8x12 micro-tile, BK=16,
// single-sync double buffer. Grid = 9*16*2 = 288 blocks = one balanced wave.
// ---------------------------------------------------------------------------
#define BM 128
#define BN 96
#define BK 16
#define NKT (DIM / BK)   // 48

__global__ __launch_bounds__(128, 2)
void gemm1_kernel(const float* __restrict__ hidden, const float* __restrict__ W1) {
    const int n0 = blockIdx.x * BN;
    const int m0 = blockIdx.y * BM;
    const float* W = W1 + (size_t)blockIdx.z * DIM * NH1;
    float* Cout = (blockIdx.z == 0) ? g_P : g_Q;

    __shared__ float As[2][BK][BM];
    __shared__ float Bs[2][BK][BN];

    const int tid = threadIdx.x;
    const int tx  = tid & 7;    // 8 col groups x 12 cols
    const int ty  = tid >> 3;   // 16 row groups x 8 rows

    float acc[8][12];
    #pragma unroll
    for (int i = 0; i < 8; i++)
        #pragma unroll
        for (int j = 0; j < 12; j++) acc[i][j] = 0.f;

    const int a_k4 = tid & 3;
    const int a_r  = tid >> 2;
    const float* aptr[4];
    #pragma unroll
    for (int rr = 0; rr < 4; rr++) {
        int m = m0 + a_r + rr * 32;
        int bb = m >> 7, t = m & 127;
        aptr[rr] = hidden + (size_t)(bb * LP1 + t + 1) * DIM + a_k4 * 4;
    }

    const int lk   = tid >> 5;
    const int lcol = tid & 31;
    bool bok[3];
    const float* bptr[3];
    #pragma unroll
    for (int c = 0; c < 3; c++) {
        int gc = n0 + lcol + 32 * c;
        bok[c]  = gc < NH1;
        bptr[c] = W + (bok[c] ? gc : 0);
    }

    float4 ra[4];
    float  rb[12];

    #pragma unroll
    for (int rr = 0; rr < 4; rr++) ra[rr] = *(const float4*)(aptr[rr]);
    #pragma unroll
    for (int k2 = 0; k2 < 4; k2++)
        #pragma unroll
        for (int c = 0; c < 3; c++)
            rb[k2*3+c] = bok[c] ? bptr[c][(size_t)(lk + 4*k2) * NH1] : 0.f;
    #pragma unroll
    for (int rr = 0; rr < 4; rr++) {
        As[0][a_k4*4+0][a_r + rr*32] = ra[rr].x;
        As[0][a_k4*4+1][a_r + rr*32] = ra[rr].y;
        As[0][a_k4*4+2][a_r + rr*32] = ra[rr].z;
        As[0][a_k4*4+3][a_r + rr*32] = ra[rr].w;
    }
    #pragma unroll
    for (int k2 = 0; k2 < 4; k2++)
        #pragma unroll
        for (int c = 0; c < 3; c++)
            Bs[0][lk + 4*k2][lcol + 32*c] = rb[k2*3+c];
    __syncthreads();

    int cur = 0;
    for (int kt = 0; kt < NKT; kt++) {
        const int k0n = (kt + 1) * BK;
        if (kt + 1 < NKT) {
            #pragma unroll
            for (int rr = 0; rr < 4; rr++) ra[rr] = *(const float4*)(aptr[rr] + k0n);
            #pragma unroll
            for (int k2 = 0; k2 < 4; k2++)
                #pragma unroll
                for (int c = 0; c < 3; c++)
                    rb[k2*3+c] = bok[c] ? bptr[c][(size_t)(k0n + lk + 4*k2) * NH1] : 0.f;
        }

        #pragma unroll
        for (int kk = 0; kk < BK; kk++) {
            float4 a0 = *(const float4*)&As[cur][kk][ty*8];
            float4 a1 = *(const float4*)&As[cur][kk][ty*8 + 4];
            float4 b0 = *(const float4*)&Bs[cur][kk][tx*12];
            float4 b1 = *(const float4*)&Bs[cur][kk][tx*12 + 4];
            float4 b2 = *(const float4*)&Bs[cur][kk][tx*12 + 8];
            float av[8]  = {a0.x,a0.y,a0.z,a0.w,a1.x,a1.y,a1.z,a1.w};
            float bv[12] = {b0.x,b0.y,b0.z,b0.w,b1.x,b1.y,b1.z,b1.w,b2.x,b2.y,b2.z,b2.w};
            #pragma unroll
            for (int i = 0; i < 8; i++)
                #pragma unroll
                for (int j = 0; j < 12; j++)
                    acc[i][j] = fmaf(av[i], bv[j], acc[i][j]);
        }

        if (kt + 1 < NKT) {
            int nxt = cur ^ 1;
            #pragma unroll
            for (int rr = 0; rr < 4; rr++) {
                As[nxt][a_k4*4+0][a_r + rr*32] = ra[rr].x;
                As[nxt][a_k4*4+1][a_r + rr*32] = ra[rr].y;
                As[nxt][a_k4*4+2][a_r + rr*32] = ra[rr].z;
                As[nxt][a_k4*4+3][a_r + rr*32] = ra[rr].w;
            }
            #pragma unroll
            for (int k2 = 0; k2 < 4; k2++)
                #pragma unroll
                for (int c = 0; c < 3; c++)
                    Bs[nxt][lk + 4*k2][lcol + 32*c] = rb[k2*3+c];
        }
        __syncthreads();
        cur ^= 1;
    }

    #pragma unroll
    for (int i = 0; i < 8; i++) {
        size_t mrow = (size_t)(m0 + ty*8 + i) * PST;
        #pragma unroll
        for (int jj = 0; jj < 3; jj++) {
            int nn = n0 + tx*12 + jj*4;
            if (nn + 3 < PST) {
                float4 v = make_float4(acc[i][jj*4+0], acc[i][jj*4+1],
                                       acc[i][jj*4+2], acc[i][jj*4+3]);
                *(float4*)(Cout + mrow + nn) = v;
            }
        }
    }
}

// ---------------------------------------------------------------------------
// Kernel 2: per (batch, 128-pair chunk):
//   Ht[k][r] = relu(P[vi_r][k] + Q[vj_r][k] + ind_r*w1c[k] + b1[k])
//   logits   = Ht^T @ W2 + b2, log_softmax fused via 8-lane shuffles.
// 256 threads (max resident warps for this one-wave grid), 4x5 micro-tile.
// ---------------------------------------------------------------------------
#define BP  128
#define BK2 32
#define HTS (BP + 4)   // 132, float4-aligned rows

__global__ __launch_bounds__(256, 2)
void span_head_kernel(const float* __restrict__ W1, const float* __restrict__ bias1,
                      const float* __restrict__ W2, const float* __restrict__ bias2,
                      const int* __restrict__ spans, float* __restrict__ out) {
    const int b   = blockIdx.y;
    const int p0  = blockIdx.x * BP;
    const int tid = threadIdx.x;   // 0..255

    __shared__ float Ht[BK2][HTS];
    __shared__ float W2s[BK2 * NOUT];
    __shared__ int   s_ri[BP];
    __shared__ int   s_rj[BP];
    __shared__ float s_ind[BP];

    const float* w1c = W1 + (size_t)2 * DIM * NH1;  // row 1536 of W1

    // Analytic pair decode: nonzero order of the (j>=i, j-i<30) band, L=128.
    if (tid < BP) {
        int p  = p0 + tid;
        int pc = (p < NPAIR) ? p : (NPAIR - 1);
        int i, j;
        if (pc < 2970) {
            i = pc / 30;
            j = i + (pc - 30 * i);
        } else {
            int q = pc - 2970;                        // 0..434, tail rows 99..127
            int d = (int)(29.5f - sqrtf(870.25f - 2.0f * (float)q));
            while ((d + 1) * (58 - d) / 2 <= q) d++;
            while (d * (59 - d) / 2 > q) d--;
            i = 99 + d;
            j = i + (q - d * (59 - d) / 2);
        }
        float ind = 0.f;
        if (p < NPAIR) {
            int s = spans[b*2 + 0];
            int e = spans[b*2 + 1];
            if (i == s && j == e)      ind = 2.f;
            else if (i >= s && j <= e) ind = 1.f;
        }
        s_ri[tid]  = (b * SEQL + i) * PST;
        s_rj[tid]  = (b * SEQL + j) * PST;
        s_ind[tid] = ind;
    }
    __syncthreads();

    const int tx   = tid & 7;    // 8 col groups x 5 outputs
    const int ty   = tid >> 3;   // 32 row groups x 4 pairs
    const int g_kq = tid & 7;    // float4 index within 32-wide k slab
    const int g_r0 = tid >> 3;   // gather rows g_r0 + 32w (w<4)

    float acc[4][5];
    #pragma unroll
    for (int i = 0; i < 4; i++)
        #pragma unroll
        for (int j = 0; j < 5; j++) acc[i][j] = 0.f;

    for (int k0 = 0; k0 < NH1; k0 += BK2) {
        // W2 tile: 32x40 = 1280 floats, 5 coalesced scalar loads per thread.
        #pragma unroll
        for (int u = 0; u < 5; u++) {
            int idx = u * 256 + tid;
            int g   = k0 * NOUT + idx;
            W2s[idx] = (g < NH1 * NOUT) ? W2[g] : 0.f;
        }

        const int kb = k0 + g_kq * 4;
        const int kl = g_kq * 4;
        if (kb < PST) {   // kb <= 768: P/Q cols valid (770/771 are zeros)
            float4 c1, c2;
            if (kb + 3 < NH1) {
                c1 = *(const float4*)(w1c + kb);
                c2 = *(const float4*)(bias1 + kb);
            } else {
                c1.x = (kb+0 < NH1) ? w1c[kb+0] : 0.f;
                c1.y = (kb+1 < NH1) ? w1c[kb+1] : 0.f;
                c1.z = (kb+2 < NH1) ? w1c[kb+2] : 0.f;
                c1.w = (kb+3 < NH1) ? w1c[kb+3] : 0.f;
                c2.x = (kb+0 < NH1) ? bias1[kb+0] : 0.f;
                c2.y = (kb+1 < NH1) ? bias1[kb+1] : 0.f;
                c2.z = (kb+2 < NH1) ? bias1[kb+2] : 0.f;
                c2.w = (kb+3 < NH1) ? bias1[kb+3] : 0.f;
            }
            #pragma unroll
            for (int w = 0; w < 4; w++) {
                int r = g_r0 + w * 32;
                float4 p4 = *(const float4*)(g_P + s_ri[r] + kb);
                float4 q4 = *(const float4*)(g_Q + s_rj[r] + kb);
                float ind = s_ind[r];
                Ht[kl+0][r] = fmaxf(fmaf(ind, c1.x, p4.x + q4.x + c2.x), 0.f);
                Ht[kl+1][r] = fmaxf(fmaf(ind, c1.y, p4.y + q4.y + c2.y), 0.f);
                Ht[kl+2][r] = fmaxf(fmaf(ind, c1.z, p4.z + q4.z + c2.z), 0.f);
                Ht[kl+3][r] = fmaxf(fmaf(ind, c1.w, p4.w + q4.w + c2.w), 0.f);
            }
        } else {          // k >= 772: P/Q pad never touched — write zeros
            #pragma unroll
            for (int w = 0; w < 4; w++) {
                int r = g_r0 + w * 32;
                Ht[kl+0][r] = 0.f; Ht[kl+1][r] = 0.f;
                Ht[kl+2][r] = 0.f; Ht[kl+3][r] = 0.f;
            }
        }
        __syncthreads();

        #pragma unroll
        for (int kk = 0; kk < BK2; kk++) {
            float4 a4 = *(const float4*)&Ht[kk][ty*4];
            const float* wrow = &W2s[kk * NOUT + tx * 5];
            float b0 = wrow[0], b1v = wrow[1], b2v = wrow[2], b3v = wrow[3], b4v = wrow[4];
            float av[4] = {a4.x, a4.y, a4.z, a4.w};
            #pragma unroll
            for (int i = 0; i < 4; i++) {
                acc[i][0] = fmaf(av[i], b0,  acc[i][0]);
                acc[i][1] = fmaf(av[i], b1v, acc[i][1]);
                acc[i][2] = fmaf(av[i], b2v, acc[i][2]);
                acc[i][3] = fmaf(av[i], b3v, acc[i][3]);
                acc[i][4] = fmaf(av[i], b4v, acc[i][4]);
            }
        }
        __syncthreads();
    }

    // bias + log_softmax per row via 8-lane butterfly (lanes tx=0..7, same ty),
    // store straight from registers.
    float bb[5];
    #pragma unroll
    for (int j = 0; j < 5; j++) bb[j] = bias2[tx*5 + j];

    #pragma unroll
    for (int i = 0; i < 4; i++) {
        float l[5];
        #pragma unroll
        for (int j = 0; j < 5; j++) l[j] = acc[i][j] + bb[j];
        float mx = l[0];
        #pragma unroll
        for (int j = 1; j < 5; j++) mx = fmaxf(mx, l[j]);
        mx = fmaxf(mx, __shfl_xor_sync(0xffffffffu, mx, 1));
        mx = fmaxf(mx, __shfl_xor_sync(0xffffffffu, mx, 2));
        mx = fmaxf(mx, __shfl_xor_sync(0xffffffffu, mx, 4));
        float sm = 0.f;
        #pragma unroll
        for (int j = 0; j < 5; j++) sm += expf(l[j] - mx);
        sm += __shfl_xor_sync(0xffffffffu, sm, 1);
        sm += __shfl_xor_sync(0xffffffffu, sm, 2);
        sm += __shfl_xor_sync(0xffffffffu, sm, 4);
        float lse = mx + logf(sm);

        int p_row = p0 + ty*4 + i;
        if (p_row < NPAIR) {
            float* op = out + ((size_t)b * NPAIR + p_row) * NOUT + tx * 5;
            #pragma unroll
            for (int j = 0; j < 5; j++) op[j] = l[j] - lse;
        }
    }
}

// ---------------------------------------------------------------------------
// Launch. Inputs (metadata order): hidden_states, pred_spans, token_num,
// span_available_indication_matrix, W1, b1, W2, b2. Output fp32 [16,3405,40].
// ---------------------------------------------------------------------------
extern "C" void kernel_launch(void* const* d_in, const int* in_sizes, int n_in,
                              void* d_out, int out_size) {
    const float* hidden = (const float*)d_in[0];
    const int*   spans  = (const int*)d_in[1];
    const float* W1 = (const float*)d_in[4];
    const float* b1 = (const float*)d_in[5];
    const float* W2 = (const float*)d_in[6];
    const float* b2 = (const float*)d_in[7];
    float* out = (float*)d_out;

    gemm1_kernel<<<dim3((NH1 + BN - 1) / BN, (BATCH * SEQL) / BM, 2), 128>>>(hidden, W1);
    span_head_kernel<<<dim3((NPAIR + BP - 1) / BP, BATCH), 256>>>(W1, b1, W2, b2, spans, out);
}

// round 9
// speedup vs baseline: 1.2049x; 1.0019x over previous
#include <cuda_runtime.h>
#include <math.h>
#include <stdint.h>

// Shapes (fixed for this problem)
#define BATCH 16
#define SEQL  128
#define DIM   768
#define NH1   770
#define NOUT  40
#define NPAIR 3405
#define LP1   129     // L+1 rows per batch in hidden_states
#define PST   772     // padded row stride for P/Q (float4-aligned)

// Scratch: P = X @ W1i, Q = X @ W1j (X = hidden[:,1:129,:] flattened, 2048 rows).
// Columns 770..771 are written as zeros (B operand cols >= 770 loaded as 0).
__device__ float g_P[(size_t)BATCH * SEQL * PST + 64];
__device__ float g_Q[(size_t)BATCH * SEQL * PST + 64];

// ---------------------------------------------------------------------------
// tf32 split helpers: x = hi + lo, both rounded to tf32 (fp32 bit layout).
// ---------------------------------------------------------------------------
__device__ __forceinline__ void split_tf32(float x, float& hi, float& lo) {
    uint32_t hb;
    asm("cvt.rna.tf32.f32 %0, %1;" : "=r"(hb) : "f"(x));
    hi = __uint_as_float(hb);
    float l = x - hi;
    uint32_t lb;
    asm("cvt.rna.tf32.f32 %0, %1;" : "=r"(lb) : "f"(l));
    lo = __uint_as_float(lb);
}

__device__ __forceinline__ void mma_tf32(float* d, const uint32_t* a,
                                         uint32_t b0, uint32_t b1) {
    asm volatile(
        "mma.sync.aligned.m16n8k8.row.col.f32.tf32.tf32.f32 "
        "{%0,%1,%2,%3}, {%4,%5,%6,%7}, {%8,%9}, {%0,%1,%2,%3};\n"
        : "+f"(d[0]), "+f"(d[1]), "+f"(d[2]), "+f"(d[3])
        : "r"(a[0]), "r"(a[1]), "r"(a[2]), "r"(a[3]), "r"(b0), "r"(b1));
}

// ---------------------------------------------------------------------------
// Kernel 1 (mma.sync tf32, 2-term split): 2048 x 896(pad of 770) x 768 GEMM.
// D = Ahi*Bhi + Ahi*Blo + Alo*Bhi, fp32 accumulate. z=0 -> P, z=1 -> Q.
// Block: 128(M) x 128(N), 256 thr = 8 warps (4M x 2N), warp tile 32x64, BK=32.
// Smem k-index swizzled: ks = k ^ ((row&3)<<3) -> conflict-free STS and LDS.
// ---------------------------------------------------------------------------
#define G_BK   32
#define G_NKT  (DIM / G_BK)        // 24
#define LDA    33                  // padded row (floats)
#define A_HI   0
#define A_LO   (128 * LDA)
#define B_HI   (2 * 128 * LDA)
#define B_LO   (3 * 128 * LDA)
#define G_SMEM (4 * 128 * LDA * 4) // 67584 bytes

__global__ __launch_bounds__(256)
void gemm1_mma(const float* __restrict__ hidden, const float* __restrict__ W1) {
    extern __shared__ float sm[];
    const int tid = threadIdx.x;
    const int wid = tid >> 5;
    const int lid = tid & 31;
    const int grp = lid >> 2;   // 0..7
    const int tig = lid & 3;    // 0..3
    const int wm  = wid & 3;    // warp M index (32 rows each)
    const int wn  = wid >> 2;   // warp N index (64 cols each)

    const int n0 = blockIdx.x * 128;
    const int m0 = blockIdx.y * 128;
    const float* W = W1 + (size_t)blockIdx.z * DIM * NH1;
    float* Cout = (blockIdx.z == 0) ? g_P : g_Q;

    float acc[2][8][4];
    #pragma unroll
    for (int mf = 0; mf < 2; mf++)
        #pragma unroll
        for (int nf = 0; nf < 8; nf++)
            #pragma unroll
            for (int c = 0; c < 4; c++) acc[mf][nf][c] = 0.f;

    // A global loader: thread t covers rows (t>>3)+32p, float4 (t&7) of 32-k slab.
    const int a_k4 = tid & 7;
    const int a_r0 = tid >> 3;
    const int bb   = m0 >> 7;   // whole tile in one batch
    const float* abase = hidden + ((size_t)bb * LP1 + 1 + (m0 & 127)) * DIM + a_k4 * 4;

    // B global loader: thread t covers column n0+(t&127), k half (t>>7)*16.
    const int  b_nl   = tid & 127;
    const int  b_kh   = tid >> 7;
    const int  ncol   = n0 + b_nl;
    const bool bok    = ncol < NH1;
    const float* bcol = W + (bok ? ncol : 0);

    for (int kt = 0; kt < G_NKT; kt++) {
        const int gk0 = kt * G_BK;
        // ---- A tile: 128 x 32, split hi/lo, swizzled store ----
        #pragma unroll
        for (int p = 0; p < 4; p++) {
            const int row = a_r0 + 32 * p;
            float4 v = *(const float4*)(abase + (size_t)row * DIM + gk0);
            const int sw = (row & 3) << 3;
            float xs[4] = {v.x, v.y, v.z, v.w};
            #pragma unroll
            for (int c = 0; c < 4; c++) {
                float hi, lo;
                split_tf32(xs[c], hi, lo);
                int ks = (a_k4 * 4 + c) ^ sw;
                sm[A_HI + row * LDA + ks] = hi;
                sm[A_LO + row * LDA + ks] = lo;
            }
        }
        // ---- B tile: 128 n-rows x 32 k (transposed read of W1), hi/lo ----
        {
            const int sw = (b_nl & 3) << 3;
            #pragma unroll
            for (int u = 0; u < 16; u++) {
                int k = b_kh * 16 + u;
                float x = bok ? bcol[(size_t)(gk0 + k) * NH1] : 0.f;
                float hi, lo;
                split_tf32(x, hi, lo);
                int ks = k ^ sw;
                sm[B_HI + b_nl * LDA + ks] = hi;
                sm[B_LO + b_nl * LDA + ks] = lo;
            }
        }
        __syncthreads();

        #pragma unroll
        for (int s = 0; s < 4; s++) {
            const int kk = s * 8;
            uint32_t ah[2][4], al[2][4];
            #pragma unroll
            for (int mf = 0; mf < 2; mf++) {
                const int mr = wm * 32 + mf * 16 + grp;      // (mr&3) == (mr+8)&3
                const int sw = (mr & 3) << 3;
                const int r0 = mr * LDA, r8 = (mr + 8) * LDA;
                const int kA = (kk + tig) ^ sw;
                const int kB = (kk + tig + 4) ^ sw;
                ah[mf][0] = __float_as_uint(sm[A_HI + r0 + kA]);
                ah[mf][1] = __float_as_uint(sm[A_HI + r8 + kA]);
                ah[mf][2] = __float_as_uint(sm[A_HI + r0 + kB]);
                ah[mf][3] = __float_as_uint(sm[A_HI + r8 + kB]);
                al[mf][0] = __float_as_uint(sm[A_LO + r0 + kA]);
                al[mf][1] = __float_as_uint(sm[A_LO + r8 + kA]);
                al[mf][2] = __float_as_uint(sm[A_LO + r0 + kB]);
                al[mf][3] = __float_as_uint(sm[A_LO + r8 + kB]);
            }
            #pragma unroll
            for (int nf = 0; nf < 8; nf++) {
                const int nr = wn * 64 + nf * 8 + grp;
                const int sw = (nr & 3) << 3;
                const int rb = nr * LDA;
                const int kA = (kk + tig) ^ sw;
                const int kB = (kk + tig + 4) ^ sw;
                uint32_t bh0 = __float_as_uint(sm[B_HI + rb + kA]);
                uint32_t bh1 = __float_as_uint(sm[B_HI + rb + kB]);
                uint32_t bl0 = __float_as_uint(sm[B_LO + rb + kA]);
                uint32_t bl1 = __float_as_uint(sm[B_LO + rb + kB]);
                #pragma unroll
                for (int mf = 0; mf < 2; mf++) {
                    mma_tf32(acc[mf][nf], ah[mf], bh0, bh1);
                    mma_tf32(acc[mf][nf], ah[mf], bl0, bl1);
                    mma_tf32(acc[mf][nf], al[mf], bh0, bh1);
                }
            }
        }
        __syncthreads();
    }

    // Epilogue: d0,d1 -> (row, 2*tig..+1); d2,d3 -> (row+8, ...).
    // Cols >= 770 hold exact zeros (B loaded 0) -> pair (770,771) zero-filled.
    #pragma unroll
    for (int mf = 0; mf < 2; mf++) {
        const int row = m0 + wm * 32 + mf * 16 + grp;
        #pragma unroll
        for (int nf = 0; nf < 8; nf++) {
            const int nn = n0 + wn * 64 + nf * 8 + tig * 2;
            if (nn + 1 < PST) {
                float* p0 = Cout + (size_t)row * PST + nn;
                float* p1 = Cout + (size_t)(row + 8) * PST + nn;
                *(float2*)p0 = make_float2(acc[mf][nf][0], acc[mf][nf][1]);
                *(float2*)p1 = make_float2(acc[mf][nf][2], acc[mf][nf][3]);
            }
        }
    }
}

// ---------------------------------------------------------------------------
// Kernel 2: per (batch, 128-pair chunk):
//   Ht[k][r] = relu(P[vi_r][k] + Q[vj_r][k] + ind_r*w1c[k] + b1[k])
//   logits   = Ht^T @ W2 + b2, log_softmax fused via 8-lane shuffles.
// 256 threads, 4x5 micro-tile. Ht columns swizzled (r ^ ((K>>3&3)<<2)) so the
// gather STS is bank-conflict-free (was 4-way).
// ---------------------------------------------------------------------------
#define BP  128
#define BK2 32
#define HTS (BP + 4)   // 132, float4-aligned rows

__global__ __launch_bounds__(256, 2)
void span_head_kernel(const float* __restrict__ W1, const float* __restrict__ bias1,
                      const float* __restrict__ W2, const float* __restrict__ bias2,
                      const int* __restrict__ spans, float* __restrict__ out) {
    const int b   = blockIdx.y;
    const int p0  = blockIdx.x * BP;
    const int tid = threadIdx.x;   // 0..255

    __shared__ float Ht[BK2][HTS];
    __shared__ float W2s[BK2 * NOUT];
    __shared__ int   s_ri[BP];
    __shared__ int   s_rj[BP];
    __shared__ float s_ind[BP];

    const float* w1c = W1 + (size_t)2 * DIM * NH1;  // row 1536 of W1

    // Analytic pair decode: nonzero order of the (j>=i, j-i<30) band, L=128.
    if (tid < BP) {
        int p  = p0 + tid;
        int pc = (p < NPAIR) ? p : (NPAIR - 1);
        int i, j;
        if (pc < 2970) {
            i = pc / 30;
            j = i + (pc - 30 * i);
        } else {
            int q = pc - 2970;                        // 0..434, tail rows 99..127
            int d = (int)(29.5f - sqrtf(870.25f - 2.0f * (float)q));
            while ((d + 1) * (58 - d) / 2 <= q) d++;
            while (d * (59 - d) / 2 > q) d--;
            i = 99 + d;
            j = i + (q - d * (59 - d) / 2);
        }
        float ind = 0.f;
        if (p < NPAIR) {
            int s = spans[b*2 + 0];
            int e = spans[b*2 + 1];
            if (i == s && j == e)      ind = 2.f;
            else if (i >= s && j <= e) ind = 1.f;
        }
        s_ri[tid]  = (b * SEQL + i) * PST;
        s_rj[tid]  = (b * SEQL + j) * PST;
        s_ind[tid] = ind;
    }
    __syncthreads();

    const int tx   = tid & 7;    // 8 col groups x 5 outputs
    const int ty   = tid >> 3;   // 32 row groups x 4 pairs
    const int g_kq = tid & 7;    // float4 index within 32-wide k slab
    const int g_r0 = tid >> 3;   // gather rows g_r0 + 32w (w<4)

    float acc[4][5];
    #pragma unroll
    for (int i = 0; i < 4; i++)
        #pragma unroll
        for (int j = 0; j < 5; j++) acc[i][j] = 0.f;

    for (int k0 = 0; k0 < NH1; k0 += BK2) {
        // W2 tile: 32x40 = 1280 floats, 5 coalesced scalar loads per thread.
        #pragma unroll
        for (int u = 0; u < 5; u++) {
            int idx = u * 256 + tid;
            int g   = k0 * NOUT + idx;
            W2s[idx] = (g < NH1 * NOUT) ? W2[g] : 0.f;
        }

        const int kb = k0 + g_kq * 4;
        const int kl = g_kq * 4;
        // column swizzle constants for rows kl..kl+3 (bank-conflict-free STS)
        const int sw0 = (((kl+0) >> 3) & 3) << 2;
        const int sw1 = (((kl+1) >> 3) & 3) << 2;
        const int sw2 = (((kl+2) >> 3) & 3) << 2;
        const int sw3 = (((kl+3) >> 3) & 3) << 2;
        if (kb < PST) {   // kb <= 768: P/Q cols valid (770/771 are zeros)
            float4 c1, c2;
            if (kb + 3 < NH1) {
                c1 = *(const float4*)(w1c + kb);
                c2 = *(const float4*)(bias1 + kb);
            } else {
                c1.x = (kb+0 < NH1) ? w1c[kb+0] : 0.f;
                c1.y = (kb+1 < NH1) ? w1c[kb+1] : 0.f;
                c1.z = (kb+2 < NH1) ? w1c[kb+2] : 0.f;
                c1.w = (kb+3 < NH1) ? w1c[kb+3] : 0.f;
                c2.x = (kb+0 < NH1) ? bias1[kb+0] : 0.f;
                c2.y = (kb+1 < NH1) ? bias1[kb+1] : 0.f;
                c2.z = (kb+2 < NH1) ? bias1[kb+2] : 0.f;
                c2.w = (kb+3 < NH1) ? bias1[kb+3] : 0.f;
            }
            #pragma unroll
            for (int w = 0; w < 4; w++) {
                int r = g_r0 + w * 32;
                float4 p4 = *(const float4*)(g_P + s_ri[r] + kb);
                float4 q4 = *(const float4*)(g_Q + s_rj[r] + kb);
                float ind = s_ind[r];
                Ht[kl+0][r ^ sw0] = fmaxf(fmaf(ind, c1.x, p4.x + q4.x + c2.x), 0.f);
                Ht[kl+1][r ^ sw1] = fmaxf(fmaf(ind, c1.y, p4.y + q4.y + c2.y), 0.f);
                Ht[kl+2][r ^ sw2] = fmaxf(fmaf(ind, c1.z, p4.z + q4.z + c2.z), 0.f);
                Ht[kl+3][r ^ sw3] = fmaxf(fmaf(ind, c1.w, p4.w + q4.w + c2.w), 0.f);
            }
        } else {          // k >= 772: P/Q pad never touched — write zeros
            #pragma unroll
            for (int w = 0; w < 4; w++) {
                int r = g_r0 + w * 32;
                Ht[kl+0][r ^ sw0] = 0.f; Ht[kl+1][r ^ sw1] = 0.f;
                Ht[kl+2][r ^ sw2] = 0.f; Ht[kl+3][r ^ sw3] = 0.f;
            }
        }
        __syncthreads();

        #pragma unroll
        for (int kk = 0; kk < BK2; kk++) {
            const int swk = ((kk >> 3) & 3) << 2;
            float4 a4 = *(const float4*)&Ht[kk][(ty*4) ^ swk];
            const float* wrow = &W2s[kk * NOUT + tx * 5];
            float b0 = wrow[0], b1v = wrow[1], b2v = wrow[2], b3v = wrow[3], b4v = wrow[4];
            float av[4] = {a4.x, a4.y, a4.z, a4.w};
            #pragma unroll
            for (int i = 0; i < 4; i++) {
                acc[i][0] = fmaf(av[i], b0,  acc[i][0]);
                acc[i][1] = fmaf(av[i], b1v, acc[i][1]);
                acc[i][2] = fmaf(av[i], b2v, acc[i][2]);
                acc[i][3] = fmaf(av[i], b3v, acc[i][3]);
                acc[i][4] = fmaf(av[i], b4v, acc[i][4]);
            }
        }
        __syncthreads();
    }

    // bias + log_softmax per row via 8-lane butterfly (lanes tx=0..7, same ty).
    float bb[5];
    #pragma unroll
    for (int j = 0; j < 5; j++) bb[j] = bias2[tx*5 + j];

    #pragma unroll
    for (int i = 0; i < 4; i++) {
        float l[5];
        #pragma unroll
        for (int j = 0; j < 5; j++) l[j] = acc[i][j] + bb[j];
        float mx = l[0];
        #pragma unroll
        for (int j = 1; j < 5; j++) mx = fmaxf(mx, l[j]);
        mx = fmaxf(mx, __shfl_xor_sync(0xffffffffu, mx, 1));
        mx = fmaxf(mx, __shfl_xor_sync(0xffffffffu, mx, 2));
        mx = fmaxf(mx, __shfl_xor_sync(0xffffffffu, mx, 4));
        float sm = 0.f;
        #pragma unroll
        for (int j = 0; j < 5; j++) sm += expf(l[j] - mx);
        sm += __shfl_xor_sync(0xffffffffu, sm, 1);
        sm += __shfl_xor_sync(0xffffffffu, sm, 2);
        sm += __shfl_xor_sync(0xffffffffu, sm, 4);
        float lse = mx + logf(sm);

        int p_row = p0 + ty*4 + i;
        if (p_row < NPAIR) {
            float* op = out + ((size_t)b * NPAIR + p_row) * NOUT + tx * 5;
            #pragma unroll
            for (int j = 0; j < 5; j++) op[j] = l[j] - lse;
        }
    }
}

// ---------------------------------------------------------------------------
// Launch. Inputs (metadata order): hidden_states, pred_spans, token_num,
// span_available_indication_matrix, W1, b1, W2, b2. Output fp32 [16,3405,40].
// ---------------------------------------------------------------------------
extern "C" void kernel_launch(void* const* d_in, const int* in_sizes, int n_in,
                              void* d_out, int out_size) {
    const float* hidden = (const float*)d_in[0];
    const int*   spans  = (const int*)d_in[1];
    const float* W1 = (const float*)d_in[4];
    const float* b1 = (const float*)d_in[5];
    const float* W2 = (const float*)d_in[6];
    const float* b2 = (const float*)d_in[7];
    float* out = (float*)d_out;

    cudaFuncSetAttribute(gemm1_mma,
                         cudaFuncAttributeMaxDynamicSharedMemorySize, G_SMEM);

    // N tiles: ceil(896/128)=7 covers 770 cols (last tile stores 768..771 only).
    gemm1_mma<<<dim3(7, (BATCH * SEQL) / 128, 2), 256, G_SMEM>>>(hidden, W1);
    span_head_kernel<<<dim3((NPAIR + BP - 1) / BP, BATCH), 256>>>(W1, b1, W2, b2, spans, out);
}

// round 10
// speedup vs baseline: 1.6252x; 1.3488x over previous
#include <cuda_runtime.h>
#include <cuda_bf16.h>
#include <math.h>
#include <stdint.h>

// Shapes (fixed for this problem)
#define BATCH 16
#define SEQL  128
#define DIM   768
#define NH1   770
#define NOUT  40
#define NPAIR 3405
#define LP1   129     // L+1 rows per batch in hidden_states
#define PST   772     // padded row stride for P/Q (float4-aligned)

// Scratch: P = X @ W1i, Q = X @ W1j (X = hidden[:,1:129,:] flattened, 2048 rows).
// Columns 770..771 are written as zeros (B operand cols >= 770 loaded as 0).
__device__ float g_P[(size_t)BATCH * SEQL * PST + 64];
__device__ float g_Q[(size_t)BATCH * SEQL * PST + 64];

// ---------------------------------------------------------------------------
// Helpers: smem addr, ldmatrix, bf16 mma, bf16 two-term split.
// ---------------------------------------------------------------------------
__device__ __forceinline__ uint32_t smem_u32(const void* p) {
    uint32_t a;
    asm("{ .reg .u64 t; cvta.to.shared.u64 t, %1; cvt.u32.u64 %0, t; }" : "=r"(a) : "l"(p));
    return a;
}
#define LDM_X4(r0, r1, r2, r3, addr) \
    asm volatile("ldmatrix.sync.aligned.m8n8.x4.shared.b16 {%0,%1,%2,%3}, [%4];" \
                 : "=r"(r0), "=r"(r1), "=r"(r2), "=r"(r3) : "r"(addr))

__device__ __forceinline__ void mma_bf16(float* d, const uint32_t* a,
                                         uint32_t b0, uint32_t b1) {
    asm volatile(
        "mma.sync.aligned.m16n8k16.row.col.f32.bf16.bf16.f32 "
        "{%0,%1,%2,%3}, {%4,%5,%6,%7}, {%8,%9}, {%0,%1,%2,%3};\n"
        : "+f"(d[0]), "+f"(d[1]), "+f"(d[2]), "+f"(d[3])
        : "r"(a[0]), "r"(a[1]), "r"(a[2]), "r"(a[3]), "r"(b0), "r"(b1));
}
// Split x0,x1 into (hi word, lo word), each word = 2 packed bf16.
__device__ __forceinline__ void split2(float x0, float x1, uint32_t& hw, uint32_t& lw) {
    __nv_bfloat16 h0 = __float2bfloat16_rn(x0);
    __nv_bfloat16 h1 = __float2bfloat16_rn(x1);
    float l0 = x0 - __bfloat162float(h0);
    float l1 = x1 - __bfloat162float(h1);
    __nv_bfloat16 g0 = __float2bfloat16_rn(l0);
    __nv_bfloat16 g1 = __float2bfloat16_rn(l1);
    hw = (uint32_t)__bfloat16_as_ushort(h0) | ((uint32_t)__bfloat16_as_ushort(h1) << 16);
    lw = (uint32_t)__bfloat16_as_ushort(g0) | ((uint32_t)__bfloat16_as_ushort(g1) << 16);
}

// ---------------------------------------------------------------------------
// Kernel 1 (bf16 mma.m16n8k16 + ldmatrix, 2-term split):
// 2048 x 896(pad of 770) x 768 GEMM. D = Ahi*Bhi + Ahi*Blo + Alo*Bhi (fp32 acc).
// z=0 -> P, z=1 -> Q. Block 128(M) x 128(N), 256 thr = 8 warps (4M x 2N),
// warp tile 32x64, BK=32. Smem rows: 32 bf16 + pad, stride 80B (ldmatrix
// conflict-free: bank(r)=20r mod 32 distinct for r=0..7).
// ---------------------------------------------------------------------------
#define G_BK  32
#define G_NKT (DIM / G_BK)   // 24
#define RS    80             // smem row stride in bytes
#define AHI_O 0
#define ALO_O (128 * RS)     // 10240
#define BHI_O (2 * 128 * RS) // 20480
#define BLO_O (3 * 128 * RS) // 30720

__global__ __launch_bounds__(256, 2)
void gemm1_mma(const float* __restrict__ hidden, const float* __restrict__ W1) {
    __shared__ __align__(16) unsigned char smbuf[4 * 128 * RS];  // 40960 B
    const uint32_t sb = smem_u32(smbuf);

    const int tid = threadIdx.x;
    const int wid = tid >> 5;
    const int lid = tid & 31;
    const int grp = lid >> 2;   // 0..7
    const int tig = lid & 3;    // 0..3
    const int wm  = wid & 3;    // warp M index (32 rows)
    const int wn  = wid >> 2;   // warp N index (64 cols)

    const int n0 = blockIdx.x * 128;
    const int m0 = blockIdx.y * 128;
    const float* W = W1 + (size_t)blockIdx.z * DIM * NH1;
    float* Cout = (blockIdx.z == 0) ? g_P : g_Q;

    float acc[2][8][4];
    #pragma unroll
    for (int mf = 0; mf < 2; mf++)
        #pragma unroll
        for (int nf = 0; nf < 8; nf++)
            #pragma unroll
            for (int c = 0; c < 4; c++) acc[mf][nf][c] = 0.f;

    // A loader: thread t -> float4 (t&7) of the 32-k slab, rows (t>>3)+32p.
    const int a_k4 = tid & 7;
    const int a_r0 = tid >> 3;
    const int bb   = m0 >> 7;   // whole M tile lies in one batch
    const float* abase = hidden + ((size_t)bb * LP1 + 1) * DIM + a_k4 * 4;

    // B loader: thread t -> column n0+(t&127), k half (t>>7)*16 .. +15.
    const int  b_nl   = tid & 127;
    const int  b_kh   = (tid >> 7) * 16;
    const int  ncol   = n0 + b_nl;
    const bool bok    = ncol < NH1;
    const float* bcol = W + (bok ? ncol : 0);

    // ldmatrix source addresses (constant per thread across k-tiles):
    //   A m16k16 tile: lanes 0-7 -> rows base+0..7 @k+0 (a0); 8-15 -> rows+8 @k+0 (a1);
    //                  16-23 -> rows+0..7 @k+8 (a2); 24-31 -> rows+8 @k+8 (a3).
    const int a_lrow = lid & 15;                 // row within 16-row tile
    const int a_lk   = (lid >> 4) << 3;          // 0 or 8
    //   B pair of n8k16 tiles: lanes 0-7 -> n base+0..7 @k+0 (b0 of nf);
    //   8-15 -> same n @k+8 (b1 of nf); 16-23 -> n+8 @k+0 (b0 of nf+1);
    //   24-31 -> n+8 @k+8 (b1 of nf+1).
    const int b_lrow = (lid & 7) + ((lid >> 4) << 3);
    const int b_lk   = ((lid >> 3) & 1) << 3;

    for (int kt = 0; kt < G_NKT; kt++) {
        const int gk0 = kt * G_BK;
        // ---- A tile: 128 x 32 fp32 -> hi/lo bf16 words ----
        #pragma unroll
        for (int p = 0; p < 4; p++) {
            const int row = a_r0 + 32 * p;
            float4 v = *(const float4*)(abase + (size_t)row * DIM + gk0);
            uint32_t h01, l01, h23, l23;
            split2(v.x, v.y, h01, l01);
            split2(v.z, v.w, h23, l23);
            const uint32_t ro = row * RS + a_k4 * 8;
            *(uint32_t*)(smbuf + AHI_O + ro)     = h01;
            *(uint32_t*)(smbuf + AHI_O + ro + 4) = h23;
            *(uint32_t*)(smbuf + ALO_O + ro)     = l01;
            *(uint32_t*)(smbuf + ALO_O + ro + 4) = l23;
        }
        // ---- B tile: 128 n-rows x 32 k (transposed W1 read), hi/lo ----
        #pragma unroll
        for (int u = 0; u < 16; u += 2) {
            const int k = b_kh + u;
            float x0 = bok ? bcol[(size_t)(gk0 + k)     * NH1] : 0.f;
            float x1 = bok ? bcol[(size_t)(gk0 + k + 1) * NH1] : 0.f;
            uint32_t hw, lw;
            split2(x0, x1, hw, lw);
            const uint32_t ro = b_nl * RS + k * 2;
            *(uint32_t*)(smbuf + BHI_O + ro) = hw;
            *(uint32_t*)(smbuf + BLO_O + ro) = lw;
        }
        __syncthreads();

        #pragma unroll
        for (int h = 0; h < 2; h++) {       // two k16 slabs per BK=32
            const int ks = h * 16;
            uint32_t ah[2][4], al[2][4];
            #pragma unroll
            for (int mf = 0; mf < 2; mf++) {
                const uint32_t ad = sb + (wm * 32 + mf * 16 + a_lrow) * RS
                                       + (ks + a_lk) * 2;
                LDM_X4(ah[mf][0], ah[mf][1], ah[mf][2], ah[mf][3], ad + AHI_O);
                LDM_X4(al[mf][0], al[mf][1], al[mf][2], al[mf][3], ad + ALO_O);
            }
            #pragma unroll
            for (int p = 0; p < 4; p++) {   // 4 pairs of n8 fragments
                const uint32_t bd = sb + (wn * 64 + p * 16 + b_lrow) * RS
                                       + (ks + b_lk) * 2;
                uint32_t bh[4], bl[4];
                LDM_X4(bh[0], bh[1], bh[2], bh[3], bd + BHI_O);
                LDM_X4(bl[0], bl[1], bl[2], bl[3], bd + BLO_O);
                #pragma unroll
                for (int q = 0; q < 2; q++) {
                    const int nf = 2 * p + q;
                    #pragma unroll
                    for (int mf = 0; mf < 2; mf++) {
                        mma_bf16(acc[mf][nf], ah[mf], bh[2*q], bh[2*q+1]);
                        mma_bf16(acc[mf][nf], ah[mf], bl[2*q], bl[2*q+1]);
                        mma_bf16(acc[mf][nf], al[mf], bh[2*q], bh[2*q+1]);
                    }
                }
            }
        }
        __syncthreads();
    }

    // Epilogue (same C layout as the verified R8 m16n8 path):
    // d0,d1 -> (row, 2*tig..+1); d2,d3 -> (row+8, ...). Cols >= 770 are zeros.
    #pragma unroll
    for (int mf = 0; mf < 2; mf++) {
        const int row = m0 + wm * 32 + mf * 16 + grp;
        #pragma unroll
        for (int nf = 0; nf < 8; nf++) {
            const int nn = n0 + wn * 64 + nf * 8 + tig * 2;
            if (nn + 1 < PST) {
                float* p0 = Cout + (size_t)row * PST + nn;
                float* p1 = Cout + (size_t)(row + 8) * PST + nn;
                *(float2*)p0 = make_float2(acc[mf][nf][0], acc[mf][nf][1]);
                *(float2*)p1 = make_float2(acc[mf][nf][2], acc[mf][nf][3]);
            }
        }
    }
}

// ---------------------------------------------------------------------------
// Kernel 2 (unchanged from R8 — measured 127.3us): per (batch, 128-pair chunk):
//   Ht[k][r] = relu(P[vi_r][k] + Q[vj_r][k] + ind_r*w1c[k] + b1[k])
//   logits   = Ht^T @ W2 + b2, log_softmax fused via 8-lane shuffles.
// ---------------------------------------------------------------------------
#define BP  128
#define BK2 32
#define HTS (BP + 4)   // 132, float4-aligned rows

__global__ __launch_bounds__(256, 2)
void span_head_kernel(const float* __restrict__ W1, const float* __restrict__ bias1,
                      const float* __restrict__ W2, const float* __restrict__ bias2,
                      const int* __restrict__ spans, float* __restrict__ out) {
    const int b   = blockIdx.y;
    const int p0  = blockIdx.x * BP;
    const int tid = threadIdx.x;   // 0..255

    __shared__ float Ht[BK2][HTS];
    __shared__ float W2s[BK2 * NOUT];
    __shared__ int   s_ri[BP];
    __shared__ int   s_rj[BP];
    __shared__ float s_ind[BP];

    const float* w1c = W1 + (size_t)2 * DIM * NH1;  // row 1536 of W1

    // Analytic pair decode: nonzero order of the (j>=i, j-i<30) band, L=128.
    if (tid < BP) {
        int p  = p0 + tid;
        int pc = (p < NPAIR) ? p : (NPAIR - 1);
        int i, j;
        if (pc < 2970) {
            i = pc / 30;
            j = i + (pc - 30 * i);
        } else {
            int q = pc - 2970;                        // 0..434, tail rows 99..127
            int d = (int)(29.5f - sqrtf(870.25f - 2.0f * (float)q));
            while ((d + 1) * (58 - d) / 2 <= q) d++;
            while (d * (59 - d) / 2 > q) d--;
            i = 99 + d;
            j = i + (q - d * (59 - d) / 2);
        }
        float ind = 0.f;
        if (p < NPAIR) {
            int s = spans[b*2 + 0];
            int e = spans[b*2 + 1];
            if (i == s && j == e)      ind = 2.f;
            else if (i >= s && j <= e) ind = 1.f;
        }
        s_ri[tid]  = (b * SEQL + i) * PST;
        s_rj[tid]  = (b * SEQL + j) * PST;
        s_ind[tid] = ind;
    }
    __syncthreads();

    const int tx   = tid & 7;    // 8 col groups x 5 outputs
    const int ty   = tid >> 3;   // 32 row groups x 4 pairs
    const int g_kq = tid & 7;    // float4 index within 32-wide k slab
    const int g_r0 = tid >> 3;   // gather rows g_r0 + 32w (w<4)

    float acc[4][5];
    #pragma unroll
    for (int i = 0; i < 4; i++)
        #pragma unroll
        for (int j = 0; j < 5; j++) acc[i][j] = 0.f;

    for (int k0 = 0; k0 < NH1; k0 += BK2) {
        // W2 tile: 32x40 = 1280 floats, 5 coalesced scalar loads per thread.
        #pragma unroll
        for (int u = 0; u < 5; u++) {
            int idx = u * 256 + tid;
            int g   = k0 * NOUT + idx;
            W2s[idx] = (g < NH1 * NOUT) ? W2[g] : 0.f;
        }

        const int kb = k0 + g_kq * 4;
        const int kl = g_kq * 4;
        // column swizzle constants for rows kl..kl+3 (bank-conflict-free STS)
        const int sw0 = (((kl+0) >> 3) & 3) << 2;
        const int sw1 = (((kl+1) >> 3) & 3) << 2;
        const int sw2 = (((kl+2) >> 3) & 3) << 2;
        const int sw3 = (((kl+3) >> 3) & 3) << 2;
        if (kb < PST) {   // kb <= 768: P/Q cols valid (770/771 are zeros)
            float4 c1, c2;
            if (kb + 3 < NH1) {
                c1 = *(const float4*)(w1c + kb);
                c2 = *(const float4*)(bias1 + kb);
            } else {
                c1.x = (kb+0 < NH1) ? w1c[kb+0] : 0.f;
                c1.y = (kb+1 < NH1) ? w1c[kb+1] : 0.f;
                c1.z = (kb+2 < NH1) ? w1c[kb+2] : 0.f;
                c1.w = (kb+3 < NH1) ? w1c[kb+3] : 0.f;
                c2.x = (kb+0 < NH1) ? bias1[kb+0] : 0.f;
                c2.y = (kb+1 < NH1) ? bias1[kb+1] : 0.f;
                c2.z = (kb+2 < NH1) ? bias1[kb+2] : 0.f;
                c2.w = (kb+3 < NH1) ? bias1[kb+3] : 0.f;
            }
            #pragma unroll
            for (int w = 0; w < 4; w++) {
                int r = g_r0 + w * 32;
                float4 p4 = *(const float4*)(g_P + s_ri[r] + kb);
                float4 q4 = *(const float4*)(g_Q + s_rj[r] + kb);
                float ind = s_ind[r];
                Ht[kl+0][r ^ sw0] = fmaxf(fmaf(ind, c1.x, p4.x + q4.x + c2.x), 0.f);
                Ht[kl+1][r ^ sw1] = fmaxf(fmaf(ind, c1.y, p4.y + q4.y + c2.y), 0.f);
                Ht[kl+2][r ^ sw2] = fmaxf(fmaf(ind, c1.z, p4.z + q4.z + c2.z), 0.f);
                Ht[kl+3][r ^ sw3] = fmaxf(fmaf(ind, c1.w, p4.w + q4.w + c2.w), 0.f);
            }
        } else {          // k >= 772: P/Q pad never touched — write zeros
            #pragma unroll
            for (int w = 0; w < 4; w++) {
                int r = g_r0 + w * 32;
                Ht[kl+0][r ^ sw0] = 0.f; Ht[kl+1][r ^ sw1] = 0.f;
                Ht[kl+2][r ^ sw2] = 0.f; Ht[kl+3][r ^ sw3] = 0.f;
            }
        }
        __syncthreads();

        #pragma unroll
        for (int kk = 0; kk < BK2; kk++) {
            const int swk = ((kk >> 3) & 3) << 2;
            float4 a4 = *(const float4*)&Ht[kk][(ty*4) ^ swk];
            const float* wrow = &W2s[kk * NOUT + tx * 5];
            float b0 = wrow[0], b1v = wrow[1], b2v = wrow[2], b3v = wrow[3], b4v = wrow[4];
            float av[4] = {a4.x, a4.y, a4.z, a4.w};
            #pragma unroll
            for (int i = 0; i < 4; i++) {
                acc[i][0] = fmaf(av[i], b0,  acc[i][0]);
                acc[i][1] = fmaf(av[i], b1v, acc[i][1]);
                acc[i][2] = fmaf(av[i], b2v, acc[i][2]);
                acc[i][3] = fmaf(av[i], b3v, acc[i][3]);
                acc[i][4] = fmaf(av[i], b4v, acc[i][4]);
            }
        }
        __syncthreads();
    }

    // bias + log_softmax per row via 8-lane butterfly (lanes tx=0..7, same ty).
    float bb[5];
    #pragma unroll
    for (int j = 0; j < 5; j++) bb[j] = bias2[tx*5 + j];

    #pragma unroll
    for (int i = 0; i < 4; i++) {
        float l[5];
        #pragma unroll
        for (int j = 0; j < 5; j++) l[j] = acc[i][j] + bb[j];
        float mx = l[0];
        #pragma unroll
        for (int j = 1; j < 5; j++) mx = fmaxf(mx, l[j]);
        mx = fmaxf(mx, __shfl_xor_sync(0xffffffffu, mx, 1));
        mx = fmaxf(mx, __shfl_xor_sync(0xffffffffu, mx, 2));
        mx = fmaxf(mx, __shfl_xor_sync(0xffffffffu, mx, 4));
        float sm = 0.f;
        #pragma unroll
        for (int j = 0; j < 5; j++) sm += expf(l[j] - mx);
        sm += __shfl_xor_sync(0xffffffffu, sm, 1);
        sm += __shfl_xor_sync(0xffffffffu, sm, 2);
        sm += __shfl_xor_sync(0xffffffffu, sm, 4);
        float lse = mx + logf(sm);

        int p_row = p0 + ty*4 + i;
        if (p_row < NPAIR) {
            float* op = out + ((size_t)b * NPAIR + p_row) * NOUT + tx * 5;
            #pragma unroll
            for (int j = 0; j < 5; j++) op[j] = l[j] - lse;
        }
    }
}

// ---------------------------------------------------------------------------
// Launch. Inputs (metadata order): hidden_states, pred_spans, token_num,
// span_available_indication_matrix, W1, b1, W2, b2. Output fp32 [16,3405,40].
// ---------------------------------------------------------------------------
extern "C" void kernel_launch(void* const* d_in, const int* in_sizes, int n_in,
                              void* d_out, int out_size) {
    const float* hidden = (const float*)d_in[0];
    const int*   spans  = (const int*)d_in[1];
    const float* W1 = (const float*)d_in[4];
    const float* b1 = (const float*)d_in[5];
    const float* W2 = (const float*)d_in[6];
    const float* b2 = (const float*)d_in[7];
    float* out = (float*)d_out;

    // N tiles: ceil(896/128)=7 covers 770 cols (last tile stores 768..771 only).
    gemm1_mma<<<dim3(7, (BATCH * SEQL) / 128, 2), 256>>>(hidden, W1);
    span_head_kernel<<<dim3((NPAIR + BP - 1) / BP, BATCH), 256>>>(W1, b1, W2, b2, spans, out);
}